// round 17
// baseline (speedup 1.0000x reference)
#include <cuda_runtime.h>
#include <math.h>

#define T_MAX   10000
#define BATCH   4096
#define CHUNK   8
#define GY      160                          // scan grid rows (chunk stride)
#define SGX     4                            // batch columns: 4*256*4 = 4096
#define NT      256
#define PNP     40                           // 256*40 = 10240 >= 10000
#define NSCAN   (SGX * GY)                   // 640 scan blocks

// fp32-cast constants, matching reference's float(np.log(...))
#define LOG_GAMMA_F  0.019802627296179713f    // log(1.02)
#define ALPHA_F     (-1.005033585350145e-05f) // log(0.99)/1000
#define INIT_LOGW_F (-1.3943265327958258f)    // log(0.248)
#define INIT_LOGP_F (-6.907755278982137f)     // log(0.001)
#define EPS_F        1e-12f
#define L1MIN_MAG    27.632f                  // |log(1e-12)| + margin (conservative)

// ---------------- device globals (zero-init is valid initial state) -----------
__device__ float    g_fv[T_MAX];      // f_t scratch
__device__ float    g_dv[T_MAX];      // d_t scratch
__device__ float    g_m[T_MAX];       // threshold m_t
__device__ float    g_c[T_MAX];       // u2 filter threshold (2.0 = never passes)
__device__ float    g_prefW[T_MAX + 1];
__device__ int      g_TcutM1;
__device__ int      g_td[BATCH];      // NEGATIVE logic: holds T_MAX - td, 0 = survivor
__device__ unsigned g_done;           // scan-block completion counter (reset each run)
__device__ unsigned g_ready;          // producer flag (reset each run)

// ---------------- acquire/release helpers -------------------------------------
__device__ __forceinline__ unsigned ld_acquire(unsigned* p) {
    unsigned v;
    asm volatile("ld.acquire.gpu.u32 %0, [%1];" : "=r"(v) : "l"(p) : "memory");
    return v;
}
__device__ __forceinline__ void st_release(unsigned* p, unsigned v) {
    asm volatile("st.release.gpu.u32 [%0], %1;" :: "l"(p), "r"(v) : "memory");
}

// ---------------- compensated fp32 (hi,lo) arithmetic -------------------------
struct DS { float hi, lo; };

__device__ __forceinline__ DS ds_make(float h) { DS r; r.hi = h; r.lo = 0.f; return r; }
__device__ __forceinline__ DS ds_of(float2 v)  { DS r; r.hi = v.x; r.lo = v.y; return r; }
__device__ __forceinline__ float2 ds_pack(DS a){ return make_float2(a.hi, a.lo); }

__device__ __forceinline__ DS ds_add(DS a, float b) {
    float s  = a.hi + b;
    float bb = s - a.hi;
    float err = (a.hi - (s - bb)) + (b - bb);
    err += a.lo;
    DS r; r.hi = s + err; r.lo = err - (r.hi - s);
    return r;
}
__device__ __forceinline__ DS ds_add2(DS a, DS b) {
    float s  = a.hi + b.hi;
    float bb = s - a.hi;
    float err = (a.hi - (s - bb)) + (b.hi - bb);
    err += a.lo + b.lo;
    DS r; r.hi = s + err; r.lo = err - (r.hi - s);
    return r;
}

__device__ __forceinline__ DS warp_scan_incl(DS v, int lane) {
    #pragma unroll
    for (int ofs = 1; ofs < 32; ofs <<= 1) {
        float h = __shfl_up_sync(0xFFFFFFFFu, v.hi, ofs);
        float l = __shfl_up_sync(0xFFFFFFFFu, v.lo, ofs);
        if (lane >= ofs) { DS t; t.hi = h; t.lo = l; v = ds_add2(v, t); }
    }
    return v;
}

// Block-exclusive DS scan, 8 warps (NT=256).
__device__ __forceinline__ DS block_excl(DS v, float2* swarp, int lane, int wid) {
    DS inc = warp_scan_incl(v, lane);
    if (lane == 31) swarp[wid] = ds_pack(inc);
    __syncthreads();
    if (wid == 0 && lane == 0) {
        DS s = ds_make(0.f);
        #pragma unroll
        for (int i = 0; i < NT / 32; i++) {
            DS t = ds_of(swarp[i]);
            swarp[i] = ds_pack(s);       // exclusive warp offsets
            s = ds_add2(s, t);
        }
    }
    __syncthreads();
    DS warpOff = ds_of(swarp[wid]);
    float hh = __shfl_up_sync(0xFFFFFFFFu, inc.hi, 1);
    float ll = __shfl_up_sync(0xFFFFFFFFu, inc.lo, 1);
    DS exw = ds_make(0.f);
    if (lane > 0) { exw.hi = hh; exw.lo = ll; }
    DS r = ds_add2(warpOff, exw);
    __syncthreads();
    return r;
}

// rare-path per-row handler; records T_MAX - t (negative logic) on first trigger
__device__ __forceinline__ void row_check(float4 v2, const float* p1row,
                                          float mi, float ci, int t,
                                          unsigned& done, int* hv) {
    float4 v1 = *(const float4*)p1row;
    if (!(done & 1u) && v2.x > ci &&
        __logf(v2.x + EPS_F) > mi * __logf(v1.x + EPS_F)) { done |= 1u; hv[0] = T_MAX - t; }
    if (!(done & 2u) && v2.y > ci &&
        __logf(v2.y + EPS_F) > mi * __logf(v1.y + EPS_F)) { done |= 2u; hv[1] = T_MAX - t; }
    if (!(done & 4u) && v2.z > ci &&
        __logf(v2.z + EPS_F) > mi * __logf(v1.z + EPS_F)) { done |= 4u; hv[2] = T_MAX - t; }
    if (!(done & 8u) && v2.w > ci &&
        __logf(v2.w + EPS_F) > mi * __logf(v1.w + EPS_F)) { done |= 8u; hv[3] = T_MAX - t; }
}

// ---------------- ONE fused kernel --------------------------------------------
__global__ __launch_bounds__(NT, 4)
void fused_kernel(const float* __restrict__ acts,
                  const float* __restrict__ u1,
                  const float* __restrict__ u2,
                  float* __restrict__ out) {
    __shared__ float2 swarp[NT / 32];
    __shared__ int    shMax;
    __shared__ bool   sLast;
    __shared__ double shd[NT];

    const int tid  = threadIdx.x;
    const int lane = tid & 31;
    const int wid  = tid >> 5;

    // ================= producer block (0,0): precompute =================
    if (blockIdx.y == 0) {
        if (blockIdx.x != 0) return;
        if (tid == 0) shMax = -1;
        const int base = tid * PNP;

        // pass 1: f,d -> scratch ; block scan of d
        DS locD = ds_make(0.f);
        #pragma unroll 4
        for (int k = 0; k < PNP; k++) {
            int t = base + k;
            if (t < T_MAX) {
                float f = __expf(acts[t]);
                float d = LOG_GAMMA_F + log1pf(-f);
                g_fv[t] = f; g_dv[t] = d;
                locD = ds_add(locD, d);
            }
        }
        __syncthreads();
        DS exD = block_excl(locD, swarp, lane, wid);

        // pass 2: local sums of e and w
        DS run = ds_add2(ds_make(INIT_LOGW_F), exD);
        DS locE = ds_make(0.f), locW = ds_make(0.f);
        #pragma unroll 4
        for (int k = 0; k < PNP; k++) {
            int t = base + k;
            if (t < T_MAX) {
                float f = g_fv[t], d = g_dv[t];
                float e = ALPHA_F * f * __expf(run.hi);   // logw BEFORE update
                locE = ds_add(locE, e);
                run = ds_add(run, d);
                float w = __expf(run.hi * 1.0e-3f);       // logw AFTER update
                locW = ds_add(locW, w);
            }
        }
        DS exE = block_excl(locE, swarp, lane, wid);
        DS exW = block_excl(locW, swarp, lane, wid);

        // pass 3: m, c, prefW, Tcut
        DS runP = ds_add2(ds_make(INIT_LOGP_F), exE);
        DS runW = exW;
        run = ds_add2(ds_make(INIT_LOGW_F), exD);
        int locMax = -1;
        #pragma unroll 4
        for (int k = 0; k < PNP; k++) {
            int t = base + k;
            if (t < T_MAX) {
                float p = __expf(runP.hi);
                float m = p / (1.0f - p) - EPS_F;
                g_m[t] = m;
                g_c[t] = (m > 0.f) ? (__expf(-L1MIN_MAG * m) - 1.0e-6f) : 2.0f;
                if (m > 0.f) locMax = t;

                float f = g_fv[t], d = g_dv[t];
                float e = ALPHA_F * f * __expf(run.hi);
                run = ds_add(run, d);
                float w = __expf(run.hi * 1.0e-3f);

                g_prefW[t] = runW.hi;
                runP = ds_add(runP, e);
                runW = ds_add(runW, w);
                if (t == T_MAX - 1) g_prefW[T_MAX] = runW.hi;
            }
        }
        atomicMax(&shMax, locMax);
        __syncthreads();
        if (tid == 0) {
            g_TcutM1 = shMax;
            __threadfence();
            st_release(&g_ready, 1u);       // publish
        }
        return;
    }

    // ================= consumer blocks: scan =================
    const int cy0 = blockIdx.y - 1;                    // first chunk index
    const int b   = (blockIdx.x * NT + tid) * 4;       // 4 consecutive batch elems

    // speculative u2 loads for first chunk (t0 < GY*CHUNK = 1280 < T_MAX, always in-bounds)
    {
        const int t0 = cy0 * CHUNK;
        float4 r[CHUNK];
        const float* p2 = u2 + (size_t)t0 * BATCH + b;
        #pragma unroll
        for (int i = 0; i < CHUNK; i++)
            r[i] = *(const float4*)(p2 + (size_t)i * BATCH);

        // wait for producer
        if (tid == 0) {
            while (ld_acquire(&g_ready) == 0u) __nanosleep(64);
        }
        __syncthreads();

        const int Tc  = g_TcutM1 + 1;
        const int nCh = (Tc + CHUNK - 1) / CHUNK;

        unsigned done = 0;
        int hv[4] = {0, 0, 0, 0};

        // process first chunk (g_c = 2.0 beyond Tcut kills dead rows for free)
        {
            bool any = false;
            bool a[CHUNK];
            float cs[CHUNK];
            #pragma unroll
            for (int i = 0; i < CHUNK; i++) {
                cs[i] = __ldg(&g_c[t0 + i]);
                float x = fmaxf(fmaxf(r[i].x, r[i].y), fmaxf(r[i].z, r[i].w));
                a[i] = x > cs[i];
                any |= a[i];
            }
            if (any) {
                const float* p1 = u1 + (size_t)t0 * BATCH + b;
                #pragma unroll
                for (int i = 0; i < CHUNK; i++) {
                    if (a[i]) {
                        row_check(r[i], p1 + (size_t)i * BATCH,
                                  __ldg(&g_m[t0 + i]), cs[i], t0 + i, done, hv);
                        if (done == 0xFu) break;
                    }
                }
            }
        }

        // remaining chunks (stride GY)
        for (int c = cy0 + GY; c < nCh && done != 0xFu; c += GY) {
            const int tt0 = c * CHUNK;
            const float* p2b = u2 + (size_t)tt0 * BATCH + b;
            float4 rr[CHUNK];
            #pragma unroll
            for (int i = 0; i < CHUNK; i++)
                rr[i] = *(const float4*)(p2b + (size_t)i * BATCH);
            bool any = false;
            bool a[CHUNK];
            float cs[CHUNK];
            #pragma unroll
            for (int i = 0; i < CHUNK; i++) {
                cs[i] = __ldg(&g_c[tt0 + i]);
                float x = fmaxf(fmaxf(rr[i].x, rr[i].y), fmaxf(rr[i].z, rr[i].w));
                a[i] = x > cs[i];
                any |= a[i];
            }
            if (any) {
                const float* p1 = u1 + (size_t)tt0 * BATCH + b;
                #pragma unroll
                for (int i = 0; i < CHUNK; i++) {
                    if (a[i] && !(done == 0xFu)) {
                        row_check(rr[i], p1 + (size_t)i * BATCH,
                                  __ldg(&g_m[tt0 + i]), cs[i], tt0 + i, done, hv);
                    }
                }
            }
        }

        // negative-logic first-death: atomicMax(T_MAX - t) == min t
        if (done & 1u) atomicMax(&g_td[b + 0], hv[0]);
        if (done & 2u) atomicMax(&g_td[b + 1], hv[1]);
        if (done & 4u) atomicMax(&g_td[b + 2], hv[2]);
        if (done & 8u) atomicMax(&g_td[b + 3], hv[3]);
    }

    // ---- completion protocol among all NSCAN scan blocks ----
    __threadfence();
    __syncthreads();
    if (tid == 0) {
        unsigned prev = atomicAdd(&g_done, 1u);
        sLast = (prev == (unsigned)NSCAN - 1u);
    }
    __syncthreads();
    if (!sLast) return;
    __threadfence();

    // ---- fused finalize: deterministic mean + state reset for next replay ----
    double s = 0.0;
    #pragma unroll
    for (int k = 0; k < BATCH / NT; k++) {
        int bb = tid + k * NT;
        int td = T_MAX - g_td[bb];        // 0 -> T_MAX (survivor)
        s += (double)g_prefW[td];
        g_td[bb] = 0;                     // reset for next run
    }
    shd[tid] = s;
    __syncthreads();
    #pragma unroll
    for (int ofs = NT / 2; ofs > 0; ofs >>= 1) {
        if (tid < ofs) shd[tid] += shd[tid + ofs];
        __syncthreads();
    }
    if (tid == 0) {
        out[0] = (float)(shd[0] * (1.0 / (double)BATCH));
        g_done  = 0u;                     // reset protocol state
        g_ready = 0u;
    }
}

// ---------------- launch -----------------------------------------------------
extern "C" void kernel_launch(void* const* d_in, const int* in_sizes, int n_in,
                              void* d_out, int out_size) {
    const float* acts = (const float*)d_in[0];
    const float* u1   = (const float*)d_in[1];
    const float* u2   = (const float*)d_in[2];
    float* out = (float*)d_out;

    dim3 grid(SGX, GY + 1);   // row 0 = producer, rows 1..GY = scan
    fused_kernel<<<grid, NT>>>(acts, u1, u2, out);
}